// round 11
// baseline (speedup 1.0000x reference)
#include <cuda_runtime.h>
#include <cuda_fp16.h>
#include <cstdint>
#include <math.h>

#define NROW    16384
#define KNBR    16
#define IN_DIM  256
#define HID_DIM 512
#define LN_EPS  1e-5f

// ---------------------------------------------------------------------------
// Low-level helpers (baseline sm_80+ instructions: valid on compute_103)
// ---------------------------------------------------------------------------
__device__ __forceinline__ uint32_t smem_u32(const void* p) {
    uint32_t a;
    asm("{ .reg .u64 t; cvta.to.shared.u64 t, %1; cvt.u32.u64 %0, t; }"
        : "=r"(a) : "l"(p));
    return a;
}
__device__ __forceinline__ void cpasync16(uint32_t dst, const void* src) {
    asm volatile("cp.async.cg.shared.global [%0], [%1], 16;" :: "r"(dst), "l"(src));
}
#define CP_COMMIT() asm volatile("cp.async.commit_group;" ::: "memory")
#define CP_WAIT(n)  asm volatile("cp.async.wait_group %0;" :: "n"(n) : "memory")

__device__ __forceinline__ void ldsm4(uint32_t* r, uint32_t addr) {
    asm volatile("ldmatrix.sync.aligned.m8n8.x4.shared.b16 {%0,%1,%2,%3}, [%4];"
        : "=r"(r[0]), "=r"(r[1]), "=r"(r[2]), "=r"(r[3]) : "r"(addr));
}
__device__ __forceinline__ void mma16816h(float* d, const uint32_t* a, const uint32_t* b) {
    asm volatile("mma.sync.aligned.m16n8k16.row.col.f32.f16.f16.f32 "
        "{%0,%1,%2,%3}, {%4,%5,%6,%7}, {%8,%9}, {%0,%1,%2,%3};"
        : "+f"(d[0]), "+f"(d[1]), "+f"(d[2]), "+f"(d[3])
        : "r"(a[0]), "r"(a[1]), "r"(a[2]), "r"(a[3]), "r"(b[0]), "r"(b[1]));
}
__device__ __forceinline__ int swz(int off) { return off ^ ((off >> 3) & 0x70); }

__device__ __forceinline__ uint32_t pack_h2(float a, float b) {
    return ((uint32_t)__half_as_ushort(__float2half_rn(b)) << 16) |
           (uint32_t)__half_as_ushort(__float2half_rn(a));
}
__device__ __forceinline__ void h8_to_f(const uint4& u, float* f) {
    const __half2* h = reinterpret_cast<const __half2*>(&u);
#pragma unroll
    for (int j = 0; j < 4; j++) {
        float2 t = __half22float2(h[j]);
        f[2 * j] = t.x; f[2 * j + 1] = t.y;
    }
}

// ---------------------------------------------------------------------------
// Scratch (device globals; no allocation allowed)
// ---------------------------------------------------------------------------
__device__ __half g_data_h[NROW * IN_DIM];
__device__ __half g_h1_h  [NROW * HID_DIM];
__device__ __half g_h2_h  [NROW * HID_DIM];
__device__ __half g_loc_h [NROW * HID_DIM];
__device__ __half g_at_h  [NROW * HID_DIM];
__device__ __half g_qh    [NROW * HID_DIM];
__device__ __half g_kh    [NROW * HID_DIM];
__device__ __half g_vh    [NROW * HID_DIM];
__device__ float g_h3   [NROW * HID_DIM];
__device__ float g_pd   [NROW * HID_DIM];
__device__ float g_inter[NROW * HID_DIM];
__device__ float g_pi   [NROW * HID_DIM];
// transposed fp16 weights: [N=512][K]
__device__ __half g_w0t[512 * 256];
__device__ __half g_w1t[512 * 512];
__device__ __half g_w2t[512 * 512];
__device__ __half g_pdt[512 * 256];
__device__ __half g_pit[512 * 256];
__device__ __half g_qt [512 * 512];
__device__ __half g_kt [512 * 512];
__device__ __half g_vt [512 * 512];
__device__ __half g_ot [512 * 512];

// ---------------------------------------------------------------------------
// Batched weight transpose + fp16 round (all 9 weights in one launch).
// ---------------------------------------------------------------------------
struct WJob { const float* W; __half* Th; int K; };
struct WJobs { WJob j[9]; };

__global__ void wsplit_all(WJobs jobs) {
    __shared__ float tile[32][33];
    const WJob jb = jobs.j[blockIdx.z];
    const int n0 = blockIdx.x * 32, k0 = blockIdx.y * 32;
    if (k0 >= jb.K) return;
    for (int i = threadIdx.y; i < 32; i += 8)
        tile[i][threadIdx.x] = jb.W[(size_t)(k0 + i) * 512 + n0 + threadIdx.x];
    __syncthreads();
    for (int i = threadIdx.y; i < 32; i += 8)
        jb.Th[(size_t)(n0 + i) * jb.K + k0 + threadIdx.x] =
            __float2half_rn(tile[threadIdx.x][i]);
}

// fp32 -> fp16 (vectorized, 8 elems/thread)
__global__ void split_f32(const float* __restrict__ x, __half* __restrict__ h, int n) {
    int i = (blockIdx.x * 256 + threadIdx.x) * 8;
    if (i >= n) return;
    float4 a = *(const float4*)(x + i);
    float4 b = *(const float4*)(x + i + 4);
    *(uint4*)(h + i) = make_uint4(pack_h2(a.x, a.y), pack_h2(a.z, a.w),
                                  pack_h2(b.x, b.y), pack_h2(b.z, b.w));
}

// ---------------------------------------------------------------------------
// HMMA GEMM: C[M,512] = act(A[M,K] @ W[K,512] + bias)
// A rounded fp16 [M,K]; W rounded fp16 [512][K] (col-major B). 1 MMA pass.
// BM=128, BN=128, BK=64, 3-stage cp.async pipeline, 256 threads
// (8 warps, 4m x 2n), warp tile 32x64 (16 MMA per 6 ldsm per kk).
// Stage = A 16KB | B 16KB = 32 KB. 2 CTAs/SM (192 KB smem).
// ---------------------------------------------------------------------------
#define STAGE_BYTES 32768
#define GEMM_SMEM   (3 * STAGE_BYTES)

template <int ACT, int WF32, int WH16>
__global__ void __launch_bounds__(256, 2)
gemm_hmma(const __half* __restrict__ Ah, const __half* __restrict__ Bw,
          const float* __restrict__ bias, float* __restrict__ Cf,
          __half* __restrict__ Ch, int Ktot) {
    extern __shared__ __align__(1024) char smem[];
    const uint32_t sb = smem_u32(smem);
    const int tid = threadIdx.x, wid = tid >> 5, lane = tid & 31;
    const int warp_m = wid & 3, warp_n = wid >> 2;   // 4 x 2
    const int bm = blockIdx.y * 128, bn = blockIdx.x * 128;

    const __half* a0 = Ah + (size_t)bm * Ktot;
    const __half* b0 = Bw + (size_t)bn * Ktot;

    float acc[2][8][4];
#pragma unroll
    for (int a = 0; a < 2; a++)
#pragma unroll
        for (int b = 0; b < 8; b++)
#pragma unroll
            for (int c = 0; c < 4; c++) acc[a][b][c] = 0.f;

    const int a_row = warp_m * 32 + (lane & 15);                          // + mt*16
    const int a_kb  = ((lane >> 4) & 1) * 16;
    const int b_row = warp_n * 64 + ((lane >> 4) & 1) * 8 + (lane & 7);   // + nt2*16
    const int b_kb  = ((lane >> 3) & 1) * 16;

    const int S = Ktot >> 6;   // >= 4 for all our GEMMs

    // 2048 16B-chunks per stage (A:1024, B:1024); 8 per thread.
    auto load_stage = [&](int buf, int k0) {
        const uint32_t st = sb + buf * STAGE_BYTES;
#pragma unroll
        for (int i = 0; i < 4; i++) {
            const int c   = tid + (i << 8);         // 0..1023
            const int row = c >> 3, kc = c & 7;
            const int so  = swz(row * 128 + kc * 16);
            const size_t go = (size_t)row * Ktot + k0 + kc * 8;
            cpasync16(st + so,         a0 + go);
            cpasync16(st + 16384 + so, b0 + go);
        }
    };

    load_stage(0, 0);  CP_COMMIT();
    load_stage(1, 64); CP_COMMIT();

    for (int s = 0; s < S; s++) {
        CP_WAIT(1);
        __syncthreads();
        if (s + 2 < S) load_stage((s + 2) % 3, (s + 2) << 6);
        CP_COMMIT();

        const uint32_t tb = sb + (s % 3) * STAGE_BYTES;
#pragma unroll
        for (int kk = 0; kk < 4; kk++) {
            uint32_t ah[8], bh[16];
#pragma unroll
            for (int mt = 0; mt < 2; mt++) {
                const int off = swz((a_row + mt * 16) * 128 + kk * 32 + a_kb);
                ldsm4(ah + 4 * mt, tb + off);
            }
#pragma unroll
            for (int nt2 = 0; nt2 < 4; nt2++) {
                const int off = swz((b_row + nt2 * 16) * 128 + kk * 32 + b_kb);
                ldsm4(bh + 4 * nt2, tb + 16384 + off);
            }
#pragma unroll
            for (int mt = 0; mt < 2; mt++)
#pragma unroll
                for (int nt = 0; nt < 8; nt++)
                    mma16816h(acc[mt][nt], ah + 4 * mt, bh + nt * 2);
        }
        __syncthreads();
    }

    // ---- epilogue: bias + act + store (fp32 and/or fp16) ----
    const int col_base = bn + warp_n * 64 + (lane & 3) * 2;
    const int row_base = bm + warp_m * 32 + (lane >> 2);
#pragma unroll
    for (int nt = 0; nt < 8; nt++) {
        const int col = col_base + nt * 8;
        const float2 bv = *(const float2*)&bias[col];
#pragma unroll
        for (int mt = 0; mt < 2; mt++) {
#pragma unroll
            for (int half_ = 0; half_ < 2; half_++) {
                const int row = row_base + mt * 16 + half_ * 8;
                float v0 = acc[mt][nt][half_ * 2 + 0] + bv.x;
                float v1 = acc[mt][nt][half_ * 2 + 1] + bv.y;
                if (ACT) {
                    v0 = v0 > 0.f ? v0 : expm1f(v0);
                    v1 = v1 > 0.f ? v1 : expm1f(v1);
                }
                if (WF32)
                    *(float2*)(Cf + (size_t)row * 512 + col) = make_float2(v0, v1);
                if (WH16)
                    *(uint32_t*)(Ch + (size_t)row * 512 + col) = pack_h2(v0, v1);
            }
        }
    }
}

// ---------------------------------------------------------------------------
// Fused residual + LayerNorm (+ optional ELU). OUT: fp32 or fp16.
// ---------------------------------------------------------------------------
template <int ACT, int H16>
__global__ void __launch_bounds__(256)
ln_res(const float* __restrict__ a, const float* __restrict__ rr, float rscale,
       const float* __restrict__ g, const float* __restrict__ b,
       float* __restrict__ of, __half* __restrict__ oh) {
    __shared__ float red[8];
    const int row = blockIdx.x, t = threadIdx.x;
    const float* ap = a  + (size_t)row * 512;
    const float* rp = rr + (size_t)row * 512;

    float x0 = ap[t]       + rscale * rp[t];
    float x1 = ap[t + 256] + rscale * rp[t + 256];

    float s = x0 + x1;
#pragma unroll
    for (int o = 16; o > 0; o >>= 1) s += __shfl_xor_sync(0xffffffffu, s, o);
    if ((t & 31) == 0) red[t >> 5] = s;
    __syncthreads();
    float mean = 0.f;
#pragma unroll
    for (int w = 0; w < 8; w++) mean += red[w];
    mean *= (1.0f / 512.0f);
    __syncthreads();

    float d0 = x0 - mean, d1 = x1 - mean;
    float vs = d0 * d0 + d1 * d1;
#pragma unroll
    for (int o = 16; o > 0; o >>= 1) vs += __shfl_xor_sync(0xffffffffu, vs, o);
    if ((t & 31) == 0) red[t >> 5] = vs;
    __syncthreads();
    float var = 0.f;
#pragma unroll
    for (int w = 0; w < 8; w++) var += red[w];
    var *= (1.0f / 512.0f);

    const float inv = rsqrtf(var + LN_EPS);
    float y0 = d0 * inv * g[t]       + b[t];
    float y1 = d1 * inv * g[t + 256] + b[t + 256];
    if (ACT) {
        y0 = y0 > 0.f ? y0 : expm1f(y0);
        y1 = y1 > 0.f ? y1 : expm1f(y1);
    }
    if (H16) {
        oh[(size_t)row * 512 + t]       = __float2half_rn(y0);
        oh[(size_t)row * 512 + t + 256] = __float2half_rn(y1);
    } else {
        of[(size_t)row * 512 + t]       = y0;
        of[(size_t)row * 512 + t + 256] = y1;
    }
}

// ---------------------------------------------------------------------------
// Neighbor attention (one warp per node). fp16 q/k/v in, fp16 out.
// ---------------------------------------------------------------------------
__global__ void __launch_bounds__(256)
nbr_attn(const __half* __restrict__ q, const __half* __restrict__ kc,
         const __half* __restrict__ vc, const int* __restrict__ nbrs,
         __half* __restrict__ oh) {
    const int warp = threadIdx.x >> 5;
    const int lane = threadIdx.x & 31;
    const int node = blockIdx.x * 8 + warp;

    const size_t base = (size_t)node * 512 + lane * 16;
    float qr[16];
    {
        uint4 u0 = *(const uint4*)(q + base);
        uint4 u1 = *(const uint4*)(q + base + 8);
        h8_to_f(u0, qr); h8_to_f(u1, qr + 8);
    }

    float m = -1e30f, s = 0.f;
    float acc[16];
#pragma unroll
    for (int i = 0; i < 16; i++) acc[i] = 0.f;

#pragma unroll
    for (int j = 0; j < KNBR; j++) {
        const int nb = __ldg(&nbrs[node * KNBR + j]);
        const __half* kp = kc + (size_t)nb * 512 + lane * 16;
        const __half* vp = vc + (size_t)nb * 512 + lane * 16;

        float kr[16], vr[16];
        uint4 k0 = *(const uint4*)kp;
        uint4 k1 = *(const uint4*)(kp + 8);
        uint4 v0 = *(const uint4*)vp;
        uint4 v1 = *(const uint4*)(vp + 8);
        h8_to_f(k0, kr); h8_to_f(k1, kr + 8);
        h8_to_f(v0, vr); h8_to_f(v1, vr + 8);

        float dot = 0.f;
#pragma unroll
        for (int i = 0; i < 16; i++) dot = fmaf(kr[i], qr[i], dot);
        dot += __shfl_xor_sync(0xffffffffu, dot, 1);
        dot += __shfl_xor_sync(0xffffffffu, dot, 2);
        const float score = dot * 0.125f;

        const float mn   = fmaxf(m, score);
        const float corr = __expf(m - mn);
        const float p    = __expf(score - mn);
        s = s * corr + p;
#pragma unroll
        for (int i = 0; i < 16; i++) acc[i] = acc[i] * corr + p * vr[i];
        m = mn;
    }

    const float inv = 1.f / s;
    uint32_t ph[8];
#pragma unroll
    for (int j = 0; j < 8; j++)
        ph[j] = pack_h2(acc[2 * j] * inv, acc[2 * j + 1] * inv);
    *(uint4*)(oh + base)     = make_uint4(ph[0], ph[1], ph[2], ph[3]);
    *(uint4*)(oh + base + 8) = make_uint4(ph[4], ph[5], ph[6], ph[7]);
}

// ---------------------------------------------------------------------------
// Launch
// ---------------------------------------------------------------------------
extern "C" void kernel_launch(void* const* d_in, const int* in_sizes, int n_in,
                              void* d_out, int out_size) {
    (void)in_sizes; (void)n_in; (void)out_size;
    const float* data   = (const float*)d_in[0];
    const int*   nbrs   = (const int*)  d_in[1];
    const float* mlp_w0 = (const float*)d_in[2];
    const float* mlp_b0 = (const float*)d_in[3];
    const float* mlp_w1 = (const float*)d_in[4];
    const float* mlp_b1 = (const float*)d_in[5];
    const float* mlp_w2 = (const float*)d_in[6];
    const float* mlp_b2 = (const float*)d_in[7];
    const float* pd_w   = (const float*)d_in[8];
    const float* pd_b   = (const float*)d_in[9];
    const float* pi_w   = (const float*)d_in[10];
    const float* pi_b   = (const float*)d_in[11];
    const float* q_w    = (const float*)d_in[12];
    const float* q_b    = (const float*)d_in[13];
    const float* k_w    = (const float*)d_in[14];
    const float* k_b    = (const float*)d_in[15];
    const float* v_w    = (const float*)d_in[16];
    const float* v_b    = (const float*)d_in[17];
    const float* o_w    = (const float*)d_in[18];
    const float* o_b    = (const float*)d_in[19];
    const float* ln1_g  = (const float*)d_in[20];
    const float* ln1_b  = (const float*)d_in[21];
    const float* ln2_g  = (const float*)d_in[22];
    const float* ln2_b  = (const float*)d_in[23];
    float* out = (float*)d_out;

    __half *data_h, *h1_h, *h2_h, *loc_h, *at_h, *qh, *kh, *vh;
    float *h3, *pd, *inter, *pi;
    __half *w0t, *w1t, *w2t, *pdt, *pit, *qt, *kt, *vt, *ot;
    cudaGetSymbolAddress((void**)&data_h, g_data_h);
    cudaGetSymbolAddress((void**)&h1_h, g_h1_h);
    cudaGetSymbolAddress((void**)&h2_h, g_h2_h);
    cudaGetSymbolAddress((void**)&loc_h, g_loc_h);
    cudaGetSymbolAddress((void**)&at_h, g_at_h);
    cudaGetSymbolAddress((void**)&qh, g_qh);   cudaGetSymbolAddress((void**)&kh, g_kh);
    cudaGetSymbolAddress((void**)&vh, g_vh);
    cudaGetSymbolAddress((void**)&h3, g_h3);   cudaGetSymbolAddress((void**)&pd, g_pd);
    cudaGetSymbolAddress((void**)&inter, g_inter);
    cudaGetSymbolAddress((void**)&pi, g_pi);
    cudaGetSymbolAddress((void**)&w0t, g_w0t); cudaGetSymbolAddress((void**)&w1t, g_w1t);
    cudaGetSymbolAddress((void**)&w2t, g_w2t); cudaGetSymbolAddress((void**)&pdt, g_pdt);
    cudaGetSymbolAddress((void**)&pit, g_pit); cudaGetSymbolAddress((void**)&qt,  g_qt);
    cudaGetSymbolAddress((void**)&kt,  g_kt);  cudaGetSymbolAddress((void**)&vt,  g_vt);
    cudaGetSymbolAddress((void**)&ot,  g_ot);

    cudaFuncSetAttribute(gemm_hmma<1, 0, 1>, cudaFuncAttributeMaxDynamicSharedMemorySize, GEMM_SMEM);
    cudaFuncSetAttribute(gemm_hmma<0, 1, 0>, cudaFuncAttributeMaxDynamicSharedMemorySize, GEMM_SMEM);
    cudaFuncSetAttribute(gemm_hmma<0, 0, 1>, cudaFuncAttributeMaxDynamicSharedMemorySize, GEMM_SMEM);

    WJobs jobs;
    jobs.j[0] = {mlp_w0, w0t, 256};
    jobs.j[1] = {mlp_w1, w1t, 512};
    jobs.j[2] = {mlp_w2, w2t, 512};
    jobs.j[3] = {pd_w,   pdt, 256};
    jobs.j[4] = {pi_w,   pit, 256};
    jobs.j[5] = {q_w,    qt,  512};
    jobs.j[6] = {k_w,    kt,  512};
    jobs.j[7] = {v_w,    vt,  512};
    jobs.j[8] = {o_w,    ot,  512};

    const dim3 gg(4, 128);   // BN=128 -> 4 column tiles

    // 0: all weight transposes (fp16 round)
    wsplit_all<<<dim3(16, 16, 9), dim3(32, 8)>>>(jobs);
    // 1: data -> fp16
    split_f32<<<(NROW * IN_DIM) / (256 * 8), 256>>>(data, data_h, NROW * IN_DIM);
    // 2..5: GEMMs
    gemm_hmma<1, 0, 1><<<gg, 256, GEMM_SMEM>>>(data_h, w0t, mlp_b0, nullptr, h1_h, 256);
    gemm_hmma<1, 0, 1><<<gg, 256, GEMM_SMEM>>>(h1_h,   w1t, mlp_b1, nullptr, h2_h, 512);
    gemm_hmma<0, 1, 0><<<gg, 256, GEMM_SMEM>>>(h2_h,   w2t, mlp_b2, h3, nullptr, 512);
    gemm_hmma<0, 1, 0><<<gg, 256, GEMM_SMEM>>>(data_h, pdt, pd_b,   pd, nullptr, 256);
    // 6: local = elu(LN(h3 + 2*pd)) -> fp16
    ln_res<1, 1><<<NROW, 256>>>(h3, pd, 2.0f, ln1_g, ln1_b, nullptr, loc_h);
    // 7-9: Q, K, V projections -> fp16
    gemm_hmma<0, 0, 1><<<gg, 256, GEMM_SMEM>>>(loc_h, qt, q_b, nullptr, qh, 512);
    gemm_hmma<0, 0, 1><<<gg, 256, GEMM_SMEM>>>(loc_h, kt, k_b, nullptr, kh, 512);
    gemm_hmma<0, 0, 1><<<gg, 256, GEMM_SMEM>>>(loc_h, vt, v_b, nullptr, vh, 512);
    // 10: neighbor attention (fp16 gather) -> fp16
    nbr_attn<<<NROW / 8, 256>>>(qh, kh, vh, nbrs, at_h);
    // 11-12: output projection + project_in
    gemm_hmma<0, 1, 0><<<gg, 256, GEMM_SMEM>>>(at_h,   ot,  o_b,  inter, nullptr, 512);
    gemm_hmma<0, 1, 0><<<gg, 256, GEMM_SMEM>>>(data_h, pit, pi_b, pi,    nullptr, 256);
    // 13: out = LN(inter + pi)
    ln_res<0, 0><<<NROW, 256>>>(inter, pi, 1.0f, ln2_g, ln2_b, out, nullptr);
}

// round 12
// speedup vs baseline: 1.6174x; 1.6174x over previous
#include <cuda_runtime.h>
#include <cuda_fp16.h>
#include <cstdint>
#include <math.h>

#define NROW    16384
#define KNBR    16
#define IN_DIM  256
#define HID_DIM 512
#define LN_EPS  1e-5f

// ---------------------------------------------------------------------------
// Low-level helpers (baseline sm_80+ instructions: valid on compute_103)
// ---------------------------------------------------------------------------
__device__ __forceinline__ uint32_t smem_u32(const void* p) {
    uint32_t a;
    asm("{ .reg .u64 t; cvta.to.shared.u64 t, %1; cvt.u32.u64 %0, t; }"
        : "=r"(a) : "l"(p));
    return a;
}
__device__ __forceinline__ void cpasync16(uint32_t dst, const void* src) {
    asm volatile("cp.async.cg.shared.global [%0], [%1], 16;" :: "r"(dst), "l"(src));
}
#define CP_COMMIT() asm volatile("cp.async.commit_group;" ::: "memory")
#define CP_WAIT(n)  asm volatile("cp.async.wait_group %0;" :: "n"(n) : "memory")

__device__ __forceinline__ void ldsm4(uint32_t* r, uint32_t addr) {
    asm volatile("ldmatrix.sync.aligned.m8n8.x4.shared.b16 {%0,%1,%2,%3}, [%4];"
        : "=r"(r[0]), "=r"(r[1]), "=r"(r[2]), "=r"(r[3]) : "r"(addr));
}
__device__ __forceinline__ void mma16816h(float* d, const uint32_t* a, const uint32_t* b) {
    asm volatile("mma.sync.aligned.m16n8k16.row.col.f32.f16.f16.f32 "
        "{%0,%1,%2,%3}, {%4,%5,%6,%7}, {%8,%9}, {%0,%1,%2,%3};"
        : "+f"(d[0]), "+f"(d[1]), "+f"(d[2]), "+f"(d[3])
        : "r"(a[0]), "r"(a[1]), "r"(a[2]), "r"(a[3]), "r"(b[0]), "r"(b[1]));
}
__device__ __forceinline__ int swz(int off) { return off ^ ((off >> 3) & 0x70); }

__device__ __forceinline__ uint32_t pack_h2(float a, float b) {
    return ((uint32_t)__half_as_ushort(__float2half_rn(b)) << 16) |
           (uint32_t)__half_as_ushort(__float2half_rn(a));
}
__device__ __forceinline__ void h8_to_f(const uint4& u, float* f) {
    const __half2* h = reinterpret_cast<const __half2*>(&u);
#pragma unroll
    for (int j = 0; j < 4; j++) {
        float2 t = __half22float2(h[j]);
        f[2 * j] = t.x; f[2 * j + 1] = t.y;
    }
}

// ---------------------------------------------------------------------------
// Scratch (device globals; no allocation allowed)
// ---------------------------------------------------------------------------
__device__ __half g_data_h[NROW * IN_DIM];
__device__ __half g_h1_h  [NROW * HID_DIM];
__device__ __half g_h2_h  [NROW * HID_DIM];
__device__ __half g_loc_h [NROW * HID_DIM];
__device__ __half g_at_h  [NROW * HID_DIM];
__device__ __half g_qh    [NROW * HID_DIM];
__device__ __half g_kh    [NROW * HID_DIM];
__device__ __half g_vh    [NROW * HID_DIM];
__device__ float g_h3   [NROW * HID_DIM];
__device__ float g_pd   [NROW * HID_DIM];
__device__ float g_inter[NROW * HID_DIM];
__device__ float g_pi   [NROW * HID_DIM];
// transposed fp16 weights: [N=512][K]
__device__ __half g_w0t[512 * 256];
__device__ __half g_w1t[512 * 512];
__device__ __half g_w2t[512 * 512];
__device__ __half g_pdt[512 * 256];
__device__ __half g_pit[512 * 256];
__device__ __half g_qt [512 * 512];
__device__ __half g_kt [512 * 512];
__device__ __half g_vt [512 * 512];
__device__ __half g_ot [512 * 512];

// ---------------------------------------------------------------------------
// Batched weight transpose + fp16 round (all 9 weights in one launch).
// ---------------------------------------------------------------------------
struct WJob { const float* W; __half* Th; int K; };
struct WJobs { WJob j[9]; };

__global__ void wsplit_all(WJobs jobs) {
    __shared__ float tile[32][33];
    const WJob jb = jobs.j[blockIdx.z];
    const int n0 = blockIdx.x * 32, k0 = blockIdx.y * 32;
    if (k0 >= jb.K) return;
    for (int i = threadIdx.y; i < 32; i += 8)
        tile[i][threadIdx.x] = jb.W[(size_t)(k0 + i) * 512 + n0 + threadIdx.x];
    __syncthreads();
    for (int i = threadIdx.y; i < 32; i += 8)
        jb.Th[(size_t)(n0 + i) * jb.K + k0 + threadIdx.x] =
            __float2half_rn(tile[threadIdx.x][i]);
}

// fp32 -> fp16 (vectorized, 8 elems/thread)
__global__ void split_f32(const float* __restrict__ x, __half* __restrict__ h, int n) {
    int i = (blockIdx.x * 256 + threadIdx.x) * 8;
    if (i >= n) return;
    float4 a = *(const float4*)(x + i);
    float4 b = *(const float4*)(x + i + 4);
    *(uint4*)(h + i) = make_uint4(pack_h2(a.x, a.y), pack_h2(a.z, a.w),
                                  pack_h2(b.x, b.y), pack_h2(b.z, b.w));
}

// ---------------------------------------------------------------------------
// HMMA GEMM, z-batched: per-z job = { A, W, bias, outputs, act }.
// C[M,512] = act(A[M,K] @ W[K,512] + bias); A,W rounded fp16; 1 MMA pass.
// BM=128, BN=64, BK=64, 4-stage cp.async pipeline, 256 threads (8 warps 4x2),
// warp tile 32x32. Stage = A 16KB | B 8KB = 24 KB. 2 CTAs/SM.
// ONE barrier per stage: the top-of-loop __syncthreads (after per-thread
// CP_WAIT) orders cp.async visibility AND the WAR hazard on buffer (s-1)&3.
// ---------------------------------------------------------------------------
#define STAGE_BYTES 24576
#define GEMM_SMEM   (4 * STAGE_BYTES)

struct GJob {
    const __half* A;      // [M,K] fp16 activations
    const __half* Bw;     // [512,K] fp16 transposed weights
    const float*  bias;   // [512]
    float*        Cf;     // fp32 output or nullptr
    __half*       Ch;     // fp16 output or nullptr
    int           act;    // 1 = ELU
};
struct GJobs { GJob j[3]; };

__global__ void __launch_bounds__(256, 2)
gemm_hmma(GJobs jobs, int Ktot) {
    extern __shared__ __align__(1024) char smem[];
    const GJob jb = jobs.j[blockIdx.z];
    const uint32_t sb = smem_u32(smem);
    const int tid = threadIdx.x, wid = tid >> 5, lane = tid & 31;
    const int warp_m = wid & 3, warp_n = wid >> 2;   // 4 x 2
    const int bm = blockIdx.y * 128, bn = blockIdx.x * 64;

    const __half* a0 = jb.A  + (size_t)bm * Ktot;
    const __half* b0 = jb.Bw + (size_t)bn * Ktot;

    float acc[2][4][4];
#pragma unroll
    for (int a = 0; a < 2; a++)
#pragma unroll
        for (int b = 0; b < 4; b++)
#pragma unroll
            for (int c = 0; c < 4; c++) acc[a][b][c] = 0.f;

    const int a_row = warp_m * 32 + (lane & 15);                          // + mt*16
    const int a_kb  = ((lane >> 4) & 1) * 16;
    const int b_row = warp_n * 32 + ((lane >> 4) & 1) * 8 + (lane & 7);   // + nt2*16
    const int b_kb  = ((lane >> 3) & 1) * 16;

    const int S = Ktot >> 6;   // >= 4 for all our GEMMs

    // 1536 16B-chunks per stage (A:1024, B:512); 6 per thread.
    auto load_stage = [&](int buf, int k0) {
        const uint32_t st = sb + buf * STAGE_BYTES;
#pragma unroll
        for (int i = 0; i < 6; i++) {
            if (i < 4) {
                const int c   = tid + (i << 8);         // 0..1023 -> A
                const int row = c >> 3, kc = c & 7;
                cpasync16(st + swz(row * 128 + kc * 16),
                          a0 + (size_t)row * Ktot + k0 + kc * 8);
            } else {
                const int c   = tid + ((i - 4) << 8);   // 0..511 -> B
                const int row = c >> 3, kc = c & 7;
                cpasync16(st + 16384 + swz(row * 128 + kc * 16),
                          b0 + (size_t)row * Ktot + k0 + kc * 8);
            }
        }
    };

    load_stage(0, 0);   CP_COMMIT();
    load_stage(1, 64);  CP_COMMIT();
    load_stage(2, 128); CP_COMMIT();

    for (int s = 0; s < S; s++) {
        CP_WAIT(2);
        __syncthreads();   // single barrier per stage (see header comment)
        if (s + 3 < S) load_stage((s + 3) & 3, (s + 3) << 6);
        CP_COMMIT();

        const uint32_t tb = sb + (s & 3) * STAGE_BYTES;
#pragma unroll
        for (int kk = 0; kk < 4; kk++) {
            uint32_t ah[8], bh[8];
#pragma unroll
            for (int mt = 0; mt < 2; mt++) {
                const int off = swz((a_row + mt * 16) * 128 + kk * 32 + a_kb);
                ldsm4(ah + 4 * mt, tb + off);
            }
#pragma unroll
            for (int nt2 = 0; nt2 < 2; nt2++) {
                const int off = swz((b_row + nt2 * 16) * 128 + kk * 32 + b_kb);
                ldsm4(bh + 4 * nt2, tb + 16384 + off);
            }
#pragma unroll
            for (int mt = 0; mt < 2; mt++)
#pragma unroll
                for (int nt = 0; nt < 4; nt++)
                    mma16816h(acc[mt][nt], ah + 4 * mt, bh + nt * 2);
        }
    }

    // ---- epilogue: bias + act + store (fp32 and/or fp16) ----
    const int col_base = bn + warp_n * 32 + (lane & 3) * 2;
    const int row_base = bm + warp_m * 32 + (lane >> 2);
#pragma unroll
    for (int nt = 0; nt < 4; nt++) {
        const int col = col_base + nt * 8;
        const float2 bv = *(const float2*)&jb.bias[col];
#pragma unroll
        for (int mt = 0; mt < 2; mt++) {
#pragma unroll
            for (int half_ = 0; half_ < 2; half_++) {
                const int row = row_base + mt * 16 + half_ * 8;
                float v0 = acc[mt][nt][half_ * 2 + 0] + bv.x;
                float v1 = acc[mt][nt][half_ * 2 + 1] + bv.y;
                if (jb.act) {
                    v0 = v0 > 0.f ? v0 : (__expf(v0) - 1.0f);
                    v1 = v1 > 0.f ? v1 : (__expf(v1) - 1.0f);
                }
                if (jb.Cf)
                    *(float2*)(jb.Cf + (size_t)row * 512 + col) = make_float2(v0, v1);
                if (jb.Ch)
                    *(uint32_t*)(jb.Ch + (size_t)row * 512 + col) = pack_h2(v0, v1);
            }
        }
    }
}

// ---------------------------------------------------------------------------
// Fused residual + LayerNorm (+ optional ELU). OUT: fp32 or fp16.
// ---------------------------------------------------------------------------
template <int ACT, int H16>
__global__ void __launch_bounds__(256)
ln_res(const float* __restrict__ a, const float* __restrict__ rr, float rscale,
       const float* __restrict__ g, const float* __restrict__ b,
       float* __restrict__ of, __half* __restrict__ oh) {
    __shared__ float red[8];
    const int row = blockIdx.x, t = threadIdx.x;
    const float* ap = a  + (size_t)row * 512;
    const float* rp = rr + (size_t)row * 512;

    float x0 = ap[t]       + rscale * rp[t];
    float x1 = ap[t + 256] + rscale * rp[t + 256];

    float s = x0 + x1;
#pragma unroll
    for (int o = 16; o > 0; o >>= 1) s += __shfl_xor_sync(0xffffffffu, s, o);
    if ((t & 31) == 0) red[t >> 5] = s;
    __syncthreads();
    float mean = 0.f;
#pragma unroll
    for (int w = 0; w < 8; w++) mean += red[w];
    mean *= (1.0f / 512.0f);
    __syncthreads();

    float d0 = x0 - mean, d1 = x1 - mean;
    float vs = d0 * d0 + d1 * d1;
#pragma unroll
    for (int o = 16; o > 0; o >>= 1) vs += __shfl_xor_sync(0xffffffffu, vs, o);
    if ((t & 31) == 0) red[t >> 5] = vs;
    __syncthreads();
    float var = 0.f;
#pragma unroll
    for (int w = 0; w < 8; w++) var += red[w];
    var *= (1.0f / 512.0f);

    const float inv = rsqrtf(var + LN_EPS);
    float y0 = d0 * inv * g[t]       + b[t];
    float y1 = d1 * inv * g[t + 256] + b[t + 256];
    if (ACT) {
        y0 = y0 > 0.f ? y0 : (__expf(y0) - 1.0f);
        y1 = y1 > 0.f ? y1 : (__expf(y1) - 1.0f);
    }
    if (H16) {
        oh[(size_t)row * 512 + t]       = __float2half_rn(y0);
        oh[(size_t)row * 512 + t + 256] = __float2half_rn(y1);
    } else {
        of[(size_t)row * 512 + t]       = y0;
        of[(size_t)row * 512 + t + 256] = y1;
    }
}

// ---------------------------------------------------------------------------
// Neighbor attention (one warp per node). fp16 q/k/v in, fp16 out.
// ---------------------------------------------------------------------------
__global__ void __launch_bounds__(256)
nbr_attn(const __half* __restrict__ q, const __half* __restrict__ kc,
         const __half* __restrict__ vc, const int* __restrict__ nbrs,
         __half* __restrict__ oh) {
    const int warp = threadIdx.x >> 5;
    const int lane = threadIdx.x & 31;
    const int node = blockIdx.x * 8 + warp;

    const size_t base = (size_t)node * 512 + lane * 16;
    float qr[16];
    {
        uint4 u0 = *(const uint4*)(q + base);
        uint4 u1 = *(const uint4*)(q + base + 8);
        h8_to_f(u0, qr); h8_to_f(u1, qr + 8);
    }

    float m = -1e30f, s = 0.f;
    float acc[16];
#pragma unroll
    for (int i = 0; i < 16; i++) acc[i] = 0.f;

#pragma unroll
    for (int j = 0; j < KNBR; j++) {
        const int nb = __ldg(&nbrs[node * KNBR + j]);
        const __half* kp = kc + (size_t)nb * 512 + lane * 16;
        const __half* vp = vc + (size_t)nb * 512 + lane * 16;

        float kr[16], vr[16];
        uint4 k0 = *(const uint4*)kp;
        uint4 k1 = *(const uint4*)(kp + 8);
        uint4 v0 = *(const uint4*)vp;
        uint4 v1 = *(const uint4*)(vp + 8);
        h8_to_f(k0, kr); h8_to_f(k1, kr + 8);
        h8_to_f(v0, vr); h8_to_f(v1, vr + 8);

        float dot = 0.f;
#pragma unroll
        for (int i = 0; i < 16; i++) dot = fmaf(kr[i], qr[i], dot);
        dot += __shfl_xor_sync(0xffffffffu, dot, 1);
        dot += __shfl_xor_sync(0xffffffffu, dot, 2);
        const float score = dot * 0.125f;

        const float mn   = fmaxf(m, score);
        const float corr = __expf(m - mn);
        const float p    = __expf(score - mn);
        s = s * corr + p;
#pragma unroll
        for (int i = 0; i < 16; i++) acc[i] = acc[i] * corr + p * vr[i];
        m = mn;
    }

    const float inv = 1.f / s;
    uint32_t ph[8];
#pragma unroll
    for (int j = 0; j < 8; j++)
        ph[j] = pack_h2(acc[2 * j] * inv, acc[2 * j + 1] * inv);
    *(uint4*)(oh + base)     = make_uint4(ph[0], ph[1], ph[2], ph[3]);
    *(uint4*)(oh + base + 8) = make_uint4(ph[4], ph[5], ph[6], ph[7]);
}

// ---------------------------------------------------------------------------
// Launch
// ---------------------------------------------------------------------------
extern "C" void kernel_launch(void* const* d_in, const int* in_sizes, int n_in,
                              void* d_out, int out_size) {
    (void)in_sizes; (void)n_in; (void)out_size;
    const float* data   = (const float*)d_in[0];
    const int*   nbrs   = (const int*)  d_in[1];
    const float* mlp_w0 = (const float*)d_in[2];
    const float* mlp_b0 = (const float*)d_in[3];
    const float* mlp_w1 = (const float*)d_in[4];
    const float* mlp_b1 = (const float*)d_in[5];
    const float* mlp_w2 = (const float*)d_in[6];
    const float* mlp_b2 = (const float*)d_in[7];
    const float* pd_w   = (const float*)d_in[8];
    const float* pd_b   = (const float*)d_in[9];
    const float* pi_w   = (const float*)d_in[10];
    const float* pi_b   = (const float*)d_in[11];
    const float* q_w    = (const float*)d_in[12];
    const float* q_b    = (const float*)d_in[13];
    const float* k_w    = (const float*)d_in[14];
    const float* k_b    = (const float*)d_in[15];
    const float* v_w    = (const float*)d_in[16];
    const float* v_b    = (const float*)d_in[17];
    const float* o_w    = (const float*)d_in[18];
    const float* o_b    = (const float*)d_in[19];
    const float* ln1_g  = (const float*)d_in[20];
    const float* ln1_b  = (const float*)d_in[21];
    const float* ln2_g  = (const float*)d_in[22];
    const float* ln2_b  = (const float*)d_in[23];
    float* out = (float*)d_out;

    __half *data_h, *h1_h, *h2_h, *loc_h, *at_h, *qh, *kh, *vh;
    float *h3, *pd, *inter, *pi;
    __half *w0t, *w1t, *w2t, *pdt, *pit, *qt, *kt, *vt, *ot;
    cudaGetSymbolAddress((void**)&data_h, g_data_h);
    cudaGetSymbolAddress((void**)&h1_h, g_h1_h);
    cudaGetSymbolAddress((void**)&h2_h, g_h2_h);
    cudaGetSymbolAddress((void**)&loc_h, g_loc_h);
    cudaGetSymbolAddress((void**)&at_h, g_at_h);
    cudaGetSymbolAddress((void**)&qh, g_qh);   cudaGetSymbolAddress((void**)&kh, g_kh);
    cudaGetSymbolAddress((void**)&vh, g_vh);
    cudaGetSymbolAddress((void**)&h3, g_h3);   cudaGetSymbolAddress((void**)&pd, g_pd);
    cudaGetSymbolAddress((void**)&inter, g_inter);
    cudaGetSymbolAddress((void**)&pi, g_pi);
    cudaGetSymbolAddress((void**)&w0t, g_w0t); cudaGetSymbolAddress((void**)&w1t, g_w1t);
    cudaGetSymbolAddress((void**)&w2t, g_w2t); cudaGetSymbolAddress((void**)&pdt, g_pdt);
    cudaGetSymbolAddress((void**)&pit, g_pit); cudaGetSymbolAddress((void**)&qt,  g_qt);
    cudaGetSymbolAddress((void**)&kt,  g_kt);  cudaGetSymbolAddress((void**)&vt,  g_vt);
    cudaGetSymbolAddress((void**)&ot,  g_ot);

    cudaFuncSetAttribute(gemm_hmma, cudaFuncAttributeMaxDynamicSharedMemorySize, GEMM_SMEM);

    WJobs wjobs;
    wjobs.j[0] = {mlp_w0, w0t, 256};
    wjobs.j[1] = {mlp_w1, w1t, 512};
    wjobs.j[2] = {mlp_w2, w2t, 512};
    wjobs.j[3] = {pd_w,   pdt, 256};
    wjobs.j[4] = {pi_w,   pit, 256};
    wjobs.j[5] = {q_w,    qt,  512};
    wjobs.j[6] = {k_w,    kt,  512};
    wjobs.j[7] = {v_w,    vt,  512};
    wjobs.j[8] = {o_w,    ot,  512};

    const dim3 gg1(8, 128, 1);   // BN=64 -> 8 column tiles
    const dim3 gg3(8, 128, 3);

    GJob z{nullptr, nullptr, nullptr, nullptr, nullptr, 0};

    // group 1: data @ {mlp0 | pd | pi}, K=256
    GJobs jA;
    jA.j[0] = {data_h, w0t, mlp_b0, nullptr, h1_h, 1};
    jA.j[1] = {data_h, pdt, pd_b,   pd,      nullptr, 0};
    jA.j[2] = {data_h, pit, pi_b,   pi,      nullptr, 0};
    // group 2: loc @ {q | k | v}, K=512
    GJobs jQ;
    jQ.j[0] = {loc_h, qt, q_b, nullptr, qh, 0};
    jQ.j[1] = {loc_h, kt, k_b, nullptr, kh, 0};
    jQ.j[2] = {loc_h, vt, v_b, nullptr, vh, 0};
    // singles
    GJobs j1; j1.j[0] = {h1_h, w1t, mlp_b1, nullptr, h2_h, 1};  j1.j[1] = z; j1.j[2] = z;
    GJobs j2; j2.j[0] = {h2_h, w2t, mlp_b2, h3, nullptr, 0};    j2.j[1] = z; j2.j[2] = z;
    GJobs jO; jO.j[0] = {at_h, ot,  o_b,    inter, nullptr, 0}; jO.j[1] = z; jO.j[2] = z;

    // 0: all weight transposes (fp16 round)
    wsplit_all<<<dim3(16, 16, 9), dim3(32, 8)>>>(wjobs);
    // 1: data -> fp16
    split_f32<<<(NROW * IN_DIM) / (256 * 8), 256>>>(data, data_h, NROW * IN_DIM);
    // 2: z-batched data GEMMs (mlp0 | pd | pi)
    gemm_hmma<<<gg3, 256, GEMM_SMEM>>>(jA, 256);
    // 3: h1 @ w1 -> h2
    gemm_hmma<<<gg1, 256, GEMM_SMEM>>>(j1, 512);
    // 4: h2 @ w2 -> h3
    gemm_hmma<<<gg1, 256, GEMM_SMEM>>>(j2, 512);
    // 5: local = elu(LN(h3 + 2*pd)) -> fp16
    ln_res<1, 1><<<NROW, 256>>>(h3, pd, 2.0f, ln1_g, ln1_b, nullptr, loc_h);
    // 6: z-batched QKV GEMMs
    gemm_hmma<<<gg3, 256, GEMM_SMEM>>>(jQ, 512);
    // 7: neighbor attention (fp16 gather) -> fp16
    nbr_attn<<<NROW / 8, 256>>>(qh, kh, vh, nbrs, at_h);
    // 8: attn @ o_w -> inter
    gemm_hmma<<<gg1, 256, GEMM_SMEM>>>(jO, 512);
    // 9: out = LN(inter + pi)
    ln_res<0, 0><<<NROW, 256>>>(inter, pi, 1.0f, ln2_g, ln2_b, out, nullptr);
}

// round 13
// speedup vs baseline: 1.6580x; 1.0251x over previous
#include <cuda_runtime.h>
#include <cuda_fp16.h>
#include <cstdint>
#include <math.h>

#define NROW    16384
#define KNBR    16
#define IN_DIM  256
#define HID_DIM 512
#define LN_EPS  1e-5f

// ---------------------------------------------------------------------------
// Low-level helpers (baseline sm_80+ instructions: valid on compute_103)
// ---------------------------------------------------------------------------
__device__ __forceinline__ uint32_t smem_u32(const void* p) {
    uint32_t a;
    asm("{ .reg .u64 t; cvta.to.shared.u64 t, %1; cvt.u32.u64 %0, t; }"
        : "=r"(a) : "l"(p));
    return a;
}
__device__ __forceinline__ void cpasync16(uint32_t dst, const void* src) {
    asm volatile("cp.async.cg.shared.global [%0], [%1], 16;" :: "r"(dst), "l"(src));
}
#define CP_COMMIT() asm volatile("cp.async.commit_group;" ::: "memory")
#define CP_WAIT(n)  asm volatile("cp.async.wait_group %0;" :: "n"(n) : "memory")

__device__ __forceinline__ void ldsm4(uint32_t* r, uint32_t addr) {
    asm volatile("ldmatrix.sync.aligned.m8n8.x4.shared.b16 {%0,%1,%2,%3}, [%4];"
        : "=r"(r[0]), "=r"(r[1]), "=r"(r[2]), "=r"(r[3]) : "r"(addr));
}
__device__ __forceinline__ void mma16816h(float* d, const uint32_t* a, const uint32_t* b) {
    asm volatile("mma.sync.aligned.m16n8k16.row.col.f32.f16.f16.f32 "
        "{%0,%1,%2,%3}, {%4,%5,%6,%7}, {%8,%9}, {%0,%1,%2,%3};"
        : "+f"(d[0]), "+f"(d[1]), "+f"(d[2]), "+f"(d[3])
        : "r"(a[0]), "r"(a[1]), "r"(a[2]), "r"(a[3]), "r"(b[0]), "r"(b[1]));
}
__device__ __forceinline__ int swz(int off) { return off ^ ((off >> 3) & 0x70); }

__device__ __forceinline__ uint32_t pack_h2(float a, float b) {
    return ((uint32_t)__half_as_ushort(__float2half_rn(b)) << 16) |
           (uint32_t)__half_as_ushort(__float2half_rn(a));
}
__device__ __forceinline__ void h8_to_f(const uint4& u, float* f) {
    const __half2* h = reinterpret_cast<const __half2*>(&u);
#pragma unroll
    for (int j = 0; j < 4; j++) {
        float2 t = __half22float2(h[j]);
        f[2 * j] = t.x; f[2 * j + 1] = t.y;
    }
}

// ---------------------------------------------------------------------------
// Scratch (device globals; no allocation allowed)
// ---------------------------------------------------------------------------
__device__ __half g_data_h[NROW * IN_DIM];
__device__ __half g_h1_h  [NROW * HID_DIM];
__device__ __half g_h2_h  [NROW * HID_DIM];
__device__ __half g_loc_h [NROW * HID_DIM];
__device__ __half g_at_h  [NROW * HID_DIM];
__device__ __half g_qh    [NROW * HID_DIM];
__device__ __half g_kh    [NROW * HID_DIM];
__device__ __half g_vh    [NROW * HID_DIM];
__device__ float g_h3   [NROW * HID_DIM];
__device__ float g_pd   [NROW * HID_DIM];
__device__ float g_inter[NROW * HID_DIM];
__device__ float g_pi   [NROW * HID_DIM];
// transposed fp16 weights: [N=512][K]
__device__ __half g_w0t[512 * 256];
__device__ __half g_w1t[512 * 512];
__device__ __half g_w2t[512 * 512];
__device__ __half g_pdt[512 * 256];
__device__ __half g_pit[512 * 256];
__device__ __half g_qt [512 * 512];
__device__ __half g_kt [512 * 512];
__device__ __half g_vt [512 * 512];
__device__ __half g_ot [512 * 512];

// ---------------------------------------------------------------------------
// Batched weight transpose + fp16 round (all 9 weights in one launch).
// ---------------------------------------------------------------------------
struct WJob { const float* W; __half* Th; int K; };
struct WJobs { WJob j[9]; };

__global__ void wsplit_all(WJobs jobs) {
    __shared__ float tile[32][33];
    const WJob jb = jobs.j[blockIdx.z];
    const int n0 = blockIdx.x * 32, k0 = blockIdx.y * 32;
    if (k0 >= jb.K) return;
    for (int i = threadIdx.y; i < 32; i += 8)
        tile[i][threadIdx.x] = jb.W[(size_t)(k0 + i) * 512 + n0 + threadIdx.x];
    __syncthreads();
    for (int i = threadIdx.y; i < 32; i += 8)
        jb.Th[(size_t)(n0 + i) * jb.K + k0 + threadIdx.x] =
            __float2half_rn(tile[threadIdx.x][i]);
}

// fp32 -> fp16 (vectorized, 8 elems/thread)
__global__ void split_f32(const float* __restrict__ x, __half* __restrict__ h, int n) {
    int i = (blockIdx.x * 256 + threadIdx.x) * 8;
    if (i >= n) return;
    float4 a = *(const float4*)(x + i);
    float4 b = *(const float4*)(x + i + 4);
    *(uint4*)(h + i) = make_uint4(pack_h2(a.x, a.y), pack_h2(a.z, a.w),
                                  pack_h2(b.x, b.y), pack_h2(b.z, b.w));
}

// ---------------------------------------------------------------------------
// HMMA GEMM, z-batched: per-z job = { A, W, bias, outputs, act }.
// C[M,512] = act(A[M,K] @ W[K,512] + bias); A,W rounded fp16; 1 MMA pass.
// BM=128, BN=64, BK=64, 3-stage cp.async pipeline, 256 threads (8 warps 4x2),
// warp tile 32x32. Stage = A 16KB | B 8KB = 24 KB. 3 CTAs/SM (216 KB smem).
// ONE barrier per stage: top-of-loop __syncthreads (after per-thread CP_WAIT)
// orders cp.async visibility AND the WAR hazard on buffer (s-1)%3.
// ---------------------------------------------------------------------------
#define STAGE_BYTES 24576
#define GEMM_SMEM   (3 * STAGE_BYTES)

struct GJob {
    const __half* A;      // [M,K] fp16 activations
    const __half* Bw;     // [512,K] fp16 transposed weights
    const float*  bias;   // [512]
    float*        Cf;     // fp32 output or nullptr
    __half*       Ch;     // fp16 output or nullptr
    int           act;    // 1 = ELU
};
struct GJobs { GJob j[3]; };

__global__ void __launch_bounds__(256, 3)
gemm_hmma(GJobs jobs, int Ktot) {
    extern __shared__ __align__(1024) char smem[];
    const GJob jb = jobs.j[blockIdx.z];
    const uint32_t sb = smem_u32(smem);
    const int tid = threadIdx.x, wid = tid >> 5, lane = tid & 31;
    const int warp_m = wid & 3, warp_n = wid >> 2;   // 4 x 2
    const int bm = blockIdx.y * 128, bn = blockIdx.x * 64;

    const __half* a0 = jb.A  + (size_t)bm * Ktot;
    const __half* b0 = jb.Bw + (size_t)bn * Ktot;

    float acc[2][4][4];
#pragma unroll
    for (int a = 0; a < 2; a++)
#pragma unroll
        for (int b = 0; b < 4; b++)
#pragma unroll
            for (int c = 0; c < 4; c++) acc[a][b][c] = 0.f;

    const int a_row = warp_m * 32 + (lane & 15);                          // + mt*16
    const int a_kb  = ((lane >> 4) & 1) * 16;
    const int b_row = warp_n * 32 + ((lane >> 4) & 1) * 8 + (lane & 7);   // + nt2*16
    const int b_kb  = ((lane >> 3) & 1) * 16;

    const int S = Ktot >> 6;   // >= 4 for all our GEMMs

    // 1536 16B-chunks per stage (A:1024, B:512); 6 per thread.
    auto load_stage = [&](int buf, int k0) {
        const uint32_t st = sb + buf * STAGE_BYTES;
#pragma unroll
        for (int i = 0; i < 6; i++) {
            if (i < 4) {
                const int c   = tid + (i << 8);         // 0..1023 -> A
                const int row = c >> 3, kc = c & 7;
                cpasync16(st + swz(row * 128 + kc * 16),
                          a0 + (size_t)row * Ktot + k0 + kc * 8);
            } else {
                const int c   = tid + ((i - 4) << 8);   // 0..511 -> B
                const int row = c >> 3, kc = c & 7;
                cpasync16(st + 16384 + swz(row * 128 + kc * 16),
                          b0 + (size_t)row * Ktot + k0 + kc * 8);
            }
        }
    };

    load_stage(0, 0);  CP_COMMIT();
    load_stage(1, 64); CP_COMMIT();

    for (int s = 0; s < S; s++) {
        CP_WAIT(1);
        __syncthreads();   // single barrier per stage (see header comment)
        if (s + 2 < S) load_stage((s + 2) % 3, (s + 2) << 6);
        CP_COMMIT();

        const uint32_t tb = sb + (s % 3) * STAGE_BYTES;
#pragma unroll
        for (int kk = 0; kk < 4; kk++) {
            uint32_t ah[8], bh[8];
#pragma unroll
            for (int mt = 0; mt < 2; mt++) {
                const int off = swz((a_row + mt * 16) * 128 + kk * 32 + a_kb);
                ldsm4(ah + 4 * mt, tb + off);
            }
#pragma unroll
            for (int nt2 = 0; nt2 < 2; nt2++) {
                const int off = swz((b_row + nt2 * 16) * 128 + kk * 32 + b_kb);
                ldsm4(bh + 4 * nt2, tb + 16384 + off);
            }
#pragma unroll
            for (int mt = 0; mt < 2; mt++)
#pragma unroll
                for (int nt = 0; nt < 4; nt++)
                    mma16816h(acc[mt][nt], ah + 4 * mt, bh + nt * 2);
        }
    }

    // ---- epilogue: bias + act + store (fp32 and/or fp16) ----
    const int col_base = bn + warp_n * 32 + (lane & 3) * 2;
    const int row_base = bm + warp_m * 32 + (lane >> 2);
#pragma unroll
    for (int nt = 0; nt < 4; nt++) {
        const int col = col_base + nt * 8;
        const float2 bv = *(const float2*)&jb.bias[col];
#pragma unroll
        for (int mt = 0; mt < 2; mt++) {
#pragma unroll
            for (int half_ = 0; half_ < 2; half_++) {
                const int row = row_base + mt * 16 + half_ * 8;
                float v0 = acc[mt][nt][half_ * 2 + 0] + bv.x;
                float v1 = acc[mt][nt][half_ * 2 + 1] + bv.y;
                if (jb.act) {
                    v0 = v0 > 0.f ? v0 : (__expf(v0) - 1.0f);
                    v1 = v1 > 0.f ? v1 : (__expf(v1) - 1.0f);
                }
                if (jb.Cf)
                    *(float2*)(jb.Cf + (size_t)row * 512 + col) = make_float2(v0, v1);
                if (jb.Ch)
                    *(uint32_t*)(jb.Ch + (size_t)row * 512 + col) = pack_h2(v0, v1);
            }
        }
    }
}

// ---------------------------------------------------------------------------
// Fused residual + LayerNorm (+ optional ELU). OUT: fp32 or fp16.
// ---------------------------------------------------------------------------
template <int ACT, int H16>
__global__ void __launch_bounds__(256)
ln_res(const float* __restrict__ a, const float* __restrict__ rr, float rscale,
       const float* __restrict__ g, const float* __restrict__ b,
       float* __restrict__ of, __half* __restrict__ oh) {
    __shared__ float red[8];
    const int row = blockIdx.x, t = threadIdx.x;
    const float* ap = a  + (size_t)row * 512;
    const float* rp = rr + (size_t)row * 512;

    float x0 = ap[t]       + rscale * rp[t];
    float x1 = ap[t + 256] + rscale * rp[t + 256];

    float s = x0 + x1;
#pragma unroll
    for (int o = 16; o > 0; o >>= 1) s += __shfl_xor_sync(0xffffffffu, s, o);
    if ((t & 31) == 0) red[t >> 5] = s;
    __syncthreads();
    float mean = 0.f;
#pragma unroll
    for (int w = 0; w < 8; w++) mean += red[w];
    mean *= (1.0f / 512.0f);
    __syncthreads();

    float d0 = x0 - mean, d1 = x1 - mean;
    float vs = d0 * d0 + d1 * d1;
#pragma unroll
    for (int o = 16; o > 0; o >>= 1) vs += __shfl_xor_sync(0xffffffffu, vs, o);
    if ((t & 31) == 0) red[t >> 5] = vs;
    __syncthreads();
    float var = 0.f;
#pragma unroll
    for (int w = 0; w < 8; w++) var += red[w];
    var *= (1.0f / 512.0f);

    const float inv = rsqrtf(var + LN_EPS);
    float y0 = d0 * inv * g[t]       + b[t];
    float y1 = d1 * inv * g[t + 256] + b[t + 256];
    if (ACT) {
        y0 = y0 > 0.f ? y0 : (__expf(y0) - 1.0f);
        y1 = y1 > 0.f ? y1 : (__expf(y1) - 1.0f);
    }
    if (H16) {
        oh[(size_t)row * 512 + t]       = __float2half_rn(y0);
        oh[(size_t)row * 512 + t + 256] = __float2half_rn(y1);
    } else {
        of[(size_t)row * 512 + t]       = y0;
        of[(size_t)row * 512 + t + 256] = y1;
    }
}

// ---------------------------------------------------------------------------
// Neighbor attention (one warp per node). fp16 q/k/v in, fp16 out.
// ---------------------------------------------------------------------------
__global__ void __launch_bounds__(256)
nbr_attn(const __half* __restrict__ q, const __half* __restrict__ kc,
         const __half* __restrict__ vc, const int* __restrict__ nbrs,
         __half* __restrict__ oh) {
    const int warp = threadIdx.x >> 5;
    const int lane = threadIdx.x & 31;
    const int node = blockIdx.x * 8 + warp;

    const size_t base = (size_t)node * 512 + lane * 16;
    float qr[16];
    {
        uint4 u0 = *(const uint4*)(q + base);
        uint4 u1 = *(const uint4*)(q + base + 8);
        h8_to_f(u0, qr); h8_to_f(u1, qr + 8);
    }

    float m = -1e30f, s = 0.f;
    float acc[16];
#pragma unroll
    for (int i = 0; i < 16; i++) acc[i] = 0.f;

#pragma unroll
    for (int j = 0; j < KNBR; j++) {
        const int nb = __ldg(&nbrs[node * KNBR + j]);
        const __half* kp = kc + (size_t)nb * 512 + lane * 16;
        const __half* vp = vc + (size_t)nb * 512 + lane * 16;

        float kr[16], vr[16];
        uint4 k0 = *(const uint4*)kp;
        uint4 k1 = *(const uint4*)(kp + 8);
        uint4 v0 = *(const uint4*)vp;
        uint4 v1 = *(const uint4*)(vp + 8);
        h8_to_f(k0, kr); h8_to_f(k1, kr + 8);
        h8_to_f(v0, vr); h8_to_f(v1, vr + 8);

        float dot = 0.f;
#pragma unroll
        for (int i = 0; i < 16; i++) dot = fmaf(kr[i], qr[i], dot);
        dot += __shfl_xor_sync(0xffffffffu, dot, 1);
        dot += __shfl_xor_sync(0xffffffffu, dot, 2);
        const float score = dot * 0.125f;

        const float mn   = fmaxf(m, score);
        const float corr = __expf(m - mn);
        const float p    = __expf(score - mn);
        s = s * corr + p;
#pragma unroll
        for (int i = 0; i < 16; i++) acc[i] = acc[i] * corr + p * vr[i];
        m = mn;
    }

    const float inv = 1.f / s;
    uint32_t ph[8];
#pragma unroll
    for (int j = 0; j < 8; j++)
        ph[j] = pack_h2(acc[2 * j] * inv, acc[2 * j + 1] * inv);
    *(uint4*)(oh + base)     = make_uint4(ph[0], ph[1], ph[2], ph[3]);
    *(uint4*)(oh + base + 8) = make_uint4(ph[4], ph[5], ph[6], ph[7]);
}

// ---------------------------------------------------------------------------
// Launch
// ---------------------------------------------------------------------------
extern "C" void kernel_launch(void* const* d_in, const int* in_sizes, int n_in,
                              void* d_out, int out_size) {
    (void)in_sizes; (void)n_in; (void)out_size;
    const float* data   = (const float*)d_in[0];
    const int*   nbrs   = (const int*)  d_in[1];
    const float* mlp_w0 = (const float*)d_in[2];
    const float* mlp_b0 = (const float*)d_in[3];
    const float* mlp_w1 = (const float*)d_in[4];
    const float* mlp_b1 = (const float*)d_in[5];
    const float* mlp_w2 = (const float*)d_in[6];
    const float* mlp_b2 = (const float*)d_in[7];
    const float* pd_w   = (const float*)d_in[8];
    const float* pd_b   = (const float*)d_in[9];
    const float* pi_w   = (const float*)d_in[10];
    const float* pi_b   = (const float*)d_in[11];
    const float* q_w    = (const float*)d_in[12];
    const float* q_b    = (const float*)d_in[13];
    const float* k_w    = (const float*)d_in[14];
    const float* k_b    = (const float*)d_in[15];
    const float* v_w    = (const float*)d_in[16];
    const float* v_b    = (const float*)d_in[17];
    const float* o_w    = (const float*)d_in[18];
    const float* o_b    = (const float*)d_in[19];
    const float* ln1_g  = (const float*)d_in[20];
    const float* ln1_b  = (const float*)d_in[21];
    const float* ln2_g  = (const float*)d_in[22];
    const float* ln2_b  = (const float*)d_in[23];
    float* out = (float*)d_out;

    __half *data_h, *h1_h, *h2_h, *loc_h, *at_h, *qh, *kh, *vh;
    float *h3, *pd, *inter, *pi;
    __half *w0t, *w1t, *w2t, *pdt, *pit, *qt, *kt, *vt, *ot;
    cudaGetSymbolAddress((void**)&data_h, g_data_h);
    cudaGetSymbolAddress((void**)&h1_h, g_h1_h);
    cudaGetSymbolAddress((void**)&h2_h, g_h2_h);
    cudaGetSymbolAddress((void**)&loc_h, g_loc_h);
    cudaGetSymbolAddress((void**)&at_h, g_at_h);
    cudaGetSymbolAddress((void**)&qh, g_qh);   cudaGetSymbolAddress((void**)&kh, g_kh);
    cudaGetSymbolAddress((void**)&vh, g_vh);
    cudaGetSymbolAddress((void**)&h3, g_h3);   cudaGetSymbolAddress((void**)&pd, g_pd);
    cudaGetSymbolAddress((void**)&inter, g_inter);
    cudaGetSymbolAddress((void**)&pi, g_pi);
    cudaGetSymbolAddress((void**)&w0t, g_w0t); cudaGetSymbolAddress((void**)&w1t, g_w1t);
    cudaGetSymbolAddress((void**)&w2t, g_w2t); cudaGetSymbolAddress((void**)&pdt, g_pdt);
    cudaGetSymbolAddress((void**)&pit, g_pit); cudaGetSymbolAddress((void**)&qt,  g_qt);
    cudaGetSymbolAddress((void**)&kt,  g_kt);  cudaGetSymbolAddress((void**)&vt,  g_vt);
    cudaGetSymbolAddress((void**)&ot,  g_ot);

    cudaFuncSetAttribute(gemm_hmma, cudaFuncAttributeMaxDynamicSharedMemorySize, GEMM_SMEM);

    WJobs wjobs;
    wjobs.j[0] = {mlp_w0, w0t, 256};
    wjobs.j[1] = {mlp_w1, w1t, 512};
    wjobs.j[2] = {mlp_w2, w2t, 512};
    wjobs.j[3] = {pd_w,   pdt, 256};
    wjobs.j[4] = {pi_w,   pit, 256};
    wjobs.j[5] = {q_w,    qt,  512};
    wjobs.j[6] = {k_w,    kt,  512};
    wjobs.j[7] = {v_w,    vt,  512};
    wjobs.j[8] = {o_w,    ot,  512};

    const dim3 gg1(8, 128, 1);   // BN=64 -> 8 column tiles
    const dim3 gg3(8, 128, 3);

    GJob z{nullptr, nullptr, nullptr, nullptr, nullptr, 0};

    // group 1: data @ {mlp0 | pd | pi}, K=256
    GJobs jA;
    jA.j[0] = {data_h, w0t, mlp_b0, nullptr, h1_h, 1};
    jA.j[1] = {data_h, pdt, pd_b,   pd,      nullptr, 0};
    jA.j[2] = {data_h, pit, pi_b,   pi,      nullptr, 0};
    // group 2: loc @ {q | k | v}, K=512
    GJobs jQ;
    jQ.j[0] = {loc_h, qt, q_b, nullptr, qh, 0};
    jQ.j[1] = {loc_h, kt, k_b, nullptr, kh, 0};
    jQ.j[2] = {loc_h, vt, v_b, nullptr, vh, 0};
    // singles
    GJobs j1; j1.j[0] = {h1_h, w1t, mlp_b1, nullptr, h2_h, 1};  j1.j[1] = z; j1.j[2] = z;
    GJobs j2; j2.j[0] = {h2_h, w2t, mlp_b2, h3, nullptr, 0};    j2.j[1] = z; j2.j[2] = z;
    GJobs jO; jO.j[0] = {at_h, ot,  o_b,    inter, nullptr, 0}; jO.j[1] = z; jO.j[2] = z;

    // 0: all weight transposes (fp16 round)
    wsplit_all<<<dim3(16, 16, 9), dim3(32, 8)>>>(wjobs);
    // 1: data -> fp16
    split_f32<<<(NROW * IN_DIM) / (256 * 8), 256>>>(data, data_h, NROW * IN_DIM);
    // 2: z-batched data GEMMs (mlp0 | pd | pi)
    gemm_hmma<<<gg3, 256, GEMM_SMEM>>>(jA, 256);
    // 3: h1 @ w1 -> h2
    gemm_hmma<<<gg1, 256, GEMM_SMEM>>>(j1, 512);
    // 4: h2 @ w2 -> h3
    gemm_hmma<<<gg1, 256, GEMM_SMEM>>>(j2, 512);
    // 5: local = elu(LN(h3 + 2*pd)) -> fp16
    ln_res<1, 1><<<NROW, 256>>>(h3, pd, 2.0f, ln1_g, ln1_b, nullptr, loc_h);
    // 6: z-batched QKV GEMMs
    gemm_hmma<<<gg3, 256, GEMM_SMEM>>>(jQ, 512);
    // 7: neighbor attention (fp16 gather) -> fp16
    nbr_attn<<<NROW / 8, 256>>>(qh, kh, vh, nbrs, at_h);
    // 8: attn @ o_w -> inter
    gemm_hmma<<<gg1, 256, GEMM_SMEM>>>(jO, 512);
    // 9: out = LN(inter + pi)
    ln_res<0, 0><<<NROW, 256>>>(inter, pi, 1.0f, ln2_g, ln2_b, out, nullptr);
}

// round 14
// speedup vs baseline: 1.7319x; 1.0445x over previous
#include <cuda_runtime.h>
#include <cuda_fp16.h>
#include <cstdint>
#include <math.h>

#define NROW    16384
#define KNBR    16
#define IN_DIM  256
#define HID_DIM 512
#define LN_EPS  1e-5f

// ---------------------------------------------------------------------------
// Low-level helpers (baseline sm_80+ instructions: valid on compute_103)
// ---------------------------------------------------------------------------
__device__ __forceinline__ uint32_t smem_u32(const void* p) {
    uint32_t a;
    asm("{ .reg .u64 t; cvta.to.shared.u64 t, %1; cvt.u32.u64 %0, t; }"
        : "=r"(a) : "l"(p));
    return a;
}
__device__ __forceinline__ void cpasync16(uint32_t dst, const void* src) {
    asm volatile("cp.async.cg.shared.global [%0], [%1], 16;" :: "r"(dst), "l"(src));
}
#define CP_COMMIT() asm volatile("cp.async.commit_group;" ::: "memory")
#define CP_WAIT(n)  asm volatile("cp.async.wait_group %0;" :: "n"(n) : "memory")

__device__ __forceinline__ void ldsm4(uint32_t* r, uint32_t addr) {
    asm volatile("ldmatrix.sync.aligned.m8n8.x4.shared.b16 {%0,%1,%2,%3}, [%4];"
        : "=r"(r[0]), "=r"(r[1]), "=r"(r[2]), "=r"(r[3]) : "r"(addr));
}
__device__ __forceinline__ void mma16816h(float* d, const uint32_t* a, const uint32_t* b) {
    asm volatile("mma.sync.aligned.m16n8k16.row.col.f32.f16.f16.f32 "
        "{%0,%1,%2,%3}, {%4,%5,%6,%7}, {%8,%9}, {%0,%1,%2,%3};"
        : "+f"(d[0]), "+f"(d[1]), "+f"(d[2]), "+f"(d[3])
        : "r"(a[0]), "r"(a[1]), "r"(a[2]), "r"(a[3]), "r"(b[0]), "r"(b[1]));
}
__device__ __forceinline__ int swz(int off) { return off ^ ((off >> 3) & 0x70); }

__device__ __forceinline__ uint32_t pack_h2(float a, float b) {
    return ((uint32_t)__half_as_ushort(__float2half_rn(b)) << 16) |
           (uint32_t)__half_as_ushort(__float2half_rn(a));
}
__device__ __forceinline__ void h8_to_f(const uint4& u, float* f) {
    const __half2* h = reinterpret_cast<const __half2*>(&u);
#pragma unroll
    for (int j = 0; j < 4; j++) {
        float2 t = __half22float2(h[j]);
        f[2 * j] = t.x; f[2 * j + 1] = t.y;
    }
}

// ---------------------------------------------------------------------------
// Scratch (device globals; no allocation allowed)
// ---------------------------------------------------------------------------
__device__ __half g_data_h[NROW * IN_DIM];
__device__ __half g_h1_h  [NROW * HID_DIM];
__device__ __half g_h2_h  [NROW * HID_DIM];
__device__ __half g_loc_h [NROW * HID_DIM];
__device__ __half g_at_h  [NROW * HID_DIM];
__device__ __half g_qh    [NROW * HID_DIM];
__device__ __half g_kh    [NROW * HID_DIM];
__device__ __half g_vh    [NROW * HID_DIM];
__device__ float g_h3   [NROW * HID_DIM];
__device__ float g_pd   [NROW * HID_DIM];
__device__ float g_inter[NROW * HID_DIM];
__device__ float g_pi   [NROW * HID_DIM];
// transposed fp16 weights: [N=512][K]
__device__ __half g_w0t[512 * 256];
__device__ __half g_w1t[512 * 512];
__device__ __half g_w2t[512 * 512];
__device__ __half g_pdt[512 * 256];
__device__ __half g_pit[512 * 256];
__device__ __half g_qt [512 * 512];
__device__ __half g_kt [512 * 512];
__device__ __half g_vt [512 * 512];
__device__ __half g_ot [512 * 512];

// ---------------------------------------------------------------------------
// Batched weight transpose + fp16 round (all 9 weights in one launch).
// ---------------------------------------------------------------------------
struct WJob { const float* W; __half* Th; int K; };
struct WJobs { WJob j[9]; };

__global__ void wsplit_all(WJobs jobs) {
    __shared__ float tile[32][33];
    const WJob jb = jobs.j[blockIdx.z];
    const int n0 = blockIdx.x * 32, k0 = blockIdx.y * 32;
    if (k0 >= jb.K) return;
    for (int i = threadIdx.y; i < 32; i += 8)
        tile[i][threadIdx.x] = jb.W[(size_t)(k0 + i) * 512 + n0 + threadIdx.x];
    __syncthreads();
    for (int i = threadIdx.y; i < 32; i += 8)
        jb.Th[(size_t)(n0 + i) * jb.K + k0 + threadIdx.x] =
            __float2half_rn(tile[threadIdx.x][i]);
}

// fp32 -> fp16 (vectorized, 8 elems/thread)
__global__ void split_f32(const float* __restrict__ x, __half* __restrict__ h, int n) {
    int i = (blockIdx.x * 256 + threadIdx.x) * 8;
    if (i >= n) return;
    float4 a = *(const float4*)(x + i);
    float4 b = *(const float4*)(x + i + 4);
    *(uint4*)(h + i) = make_uint4(pack_h2(a.x, a.y), pack_h2(a.z, a.w),
                                  pack_h2(b.x, b.y), pack_h2(b.z, b.w));
}

// ---------------------------------------------------------------------------
// HMMA GEMM, z-batched: per-z job = { A, W, bias, outputs, act }.
// C[M,512] = act(A[M,K] @ W[K,512] + bias); A,W rounded fp16; 1 MMA pass.
// BM=128, BN=64, BK=64, 3-stage cp.async pipeline, 256 threads (8 warps 4x2),
// warp tile 32x32. Stage = A 16KB | B 8KB = 24 KB. 3 CTAs/SM (216 KB smem).
// Addressing strength-reduced: swz(X + kk*32) == swz(X) ^ (kk*32) because
// bits 5-6 of X are zero (kb<=16, row*128) so kk*32 neither carries into
// bit 7 nor alters the swizzle mask; ldsm bases and cp.async smem offsets
// are computed ONCE and reused every stage.
// ---------------------------------------------------------------------------
#define STAGE_BYTES 24576
#define GEMM_SMEM   (3 * STAGE_BYTES)

struct GJob {
    const __half* A;      // [M,K] fp16 activations
    const __half* Bw;     // [512,K] fp16 transposed weights
    const float*  bias;   // [512]
    float*        Cf;     // fp32 output or nullptr
    __half*       Ch;     // fp16 output or nullptr
    int           act;    // 1 = ELU
};
struct GJobs { GJob j[3]; };

__global__ void __launch_bounds__(256, 3)
gemm_hmma(GJobs jobs, int Ktot) {
    extern __shared__ __align__(1024) char smem[];
    const GJob jb = jobs.j[blockIdx.z];
    const uint32_t sb = smem_u32(smem);
    const int tid = threadIdx.x, wid = tid >> 5, lane = tid & 31;
    const int warp_m = wid & 3, warp_n = wid >> 2;   // 4 x 2
    const int bm = blockIdx.y * 128, bn = blockIdx.x * 64;

    float acc[2][4][4];
#pragma unroll
    for (int a = 0; a < 2; a++)
#pragma unroll
        for (int b = 0; b < 4; b++)
#pragma unroll
            for (int c = 0; c < 4; c++) acc[a][b][c] = 0.f;

    // ---- precomputed ldsm bases (kk-invariant, stage-invariant) ----
    const int a_row = warp_m * 32 + (lane & 15);
    const int a_kb  = ((lane >> 4) & 1) * 16;
    const int b_row = warp_n * 32 + ((lane >> 4) & 1) * 8 + (lane & 7);
    const int b_kb  = ((lane >> 3) & 1) * 16;
    const uint32_t abase0 = swz(a_row * 128 + a_kb);
    const uint32_t abase1 = swz((a_row + 16) * 128 + a_kb);
    const uint32_t bbase0 = swz(b_row * 128 + b_kb) + 16384u;
    const uint32_t bbase1 = swz((b_row + 16) * 128 + b_kb) + 16384u;

    // ---- precomputed cp.async mapping (stage-invariant) ----
    // chunk c = tid + i*256: row = c>>3, kc = c&7. A uses i=0..3, B i=0..1;
    // chunk i shares its swizzled smem offset between A and B.
    uint32_t soff[4];
#pragma unroll
    for (int i = 0; i < 4; i++) {
        const int c = tid + (i << 8);
        soff[i] = swz((c >> 3) * 128 + (c & 7) * 16);
    }
    const size_t gbase   = (size_t)(tid >> 3) * Ktot + (tid & 7) * 8;
    const size_t gstride = (size_t)32 * Ktot;          // 32 rows per chunk step
    const __half* gA = jb.A  + (size_t)bm * Ktot + gbase;
    const __half* gB = jb.Bw + (size_t)bn * Ktot + gbase;

    const int S = Ktot >> 6;   // >= 4 for all our GEMMs

    auto load_stage = [&](int buf, int k0) {
        const uint32_t st = sb + buf * STAGE_BYTES;
#pragma unroll
        for (int i = 0; i < 4; i++)
            cpasync16(st + soff[i], gA + i * gstride + k0);
#pragma unroll
        for (int i = 0; i < 2; i++)
            cpasync16(st + 16384u + soff[i], gB + i * gstride + k0);
    };

    load_stage(0, 0);  CP_COMMIT();
    load_stage(1, 64); CP_COMMIT();

    for (int s = 0; s < S; s++) {
        CP_WAIT(1);
        __syncthreads();   // orders cp.async visibility AND WAR on buffer (s-1)%3
        if (s + 2 < S) load_stage((s + 2) % 3, (s + 2) << 6);
        CP_COMMIT();

        const uint32_t tb = sb + (s % 3) * STAGE_BYTES;
#pragma unroll
        for (int kk = 0; kk < 4; kk++) {
            const uint32_t kx = kk << 5;
            uint32_t ah[8], bh[8];
            ldsm4(ah,     tb + (abase0 ^ kx));
            ldsm4(ah + 4, tb + (abase1 ^ kx));
            ldsm4(bh,     tb + (bbase0 ^ kx));
            ldsm4(bh + 4, tb + (bbase1 ^ kx));
#pragma unroll
            for (int mt = 0; mt < 2; mt++)
#pragma unroll
                for (int nt = 0; nt < 4; nt++)
                    mma16816h(acc[mt][nt], ah + 4 * mt, bh + nt * 2);
        }
    }

    // ---- epilogue: bias + act + store (fp32 and/or fp16) ----
    const int col_base = bn + warp_n * 32 + (lane & 3) * 2;
    const int row_base = bm + warp_m * 32 + (lane >> 2);
#pragma unroll
    for (int nt = 0; nt < 4; nt++) {
        const int col = col_base + nt * 8;
        const float2 bv = *(const float2*)&jb.bias[col];
#pragma unroll
        for (int mt = 0; mt < 2; mt++) {
#pragma unroll
            for (int half_ = 0; half_ < 2; half_++) {
                const int row = row_base + mt * 16 + half_ * 8;
                float v0 = acc[mt][nt][half_ * 2 + 0] + bv.x;
                float v1 = acc[mt][nt][half_ * 2 + 1] + bv.y;
                if (jb.act) {
                    v0 = v0 > 0.f ? v0 : (__expf(v0) - 1.0f);
                    v1 = v1 > 0.f ? v1 : (__expf(v1) - 1.0f);
                }
                if (jb.Cf)
                    *(float2*)(jb.Cf + (size_t)row * 512 + col) = make_float2(v0, v1);
                if (jb.Ch)
                    *(uint32_t*)(jb.Ch + (size_t)row * 512 + col) = pack_h2(v0, v1);
            }
        }
    }
}

// ---------------------------------------------------------------------------
// Fused residual + LayerNorm (+ optional ELU). OUT: fp32 or fp16.
// ---------------------------------------------------------------------------
template <int ACT, int H16>
__global__ void __launch_bounds__(256)
ln_res(const float* __restrict__ a, const float* __restrict__ rr, float rscale,
       const float* __restrict__ g, const float* __restrict__ b,
       float* __restrict__ of, __half* __restrict__ oh) {
    __shared__ float red[8];
    const int row = blockIdx.x, t = threadIdx.x;
    const float* ap = a  + (size_t)row * 512;
    const float* rp = rr + (size_t)row * 512;

    float x0 = ap[t]       + rscale * rp[t];
    float x1 = ap[t + 256] + rscale * rp[t + 256];

    float s = x0 + x1;
#pragma unroll
    for (int o = 16; o > 0; o >>= 1) s += __shfl_xor_sync(0xffffffffu, s, o);
    if ((t & 31) == 0) red[t >> 5] = s;
    __syncthreads();
    float mean = 0.f;
#pragma unroll
    for (int w = 0; w < 8; w++) mean += red[w];
    mean *= (1.0f / 512.0f);
    __syncthreads();

    float d0 = x0 - mean, d1 = x1 - mean;
    float vs = d0 * d0 + d1 * d1;
#pragma unroll
    for (int o = 16; o > 0; o >>= 1) vs += __shfl_xor_sync(0xffffffffu, vs, o);
    if ((t & 31) == 0) red[t >> 5] = vs;
    __syncthreads();
    float var = 0.f;
#pragma unroll
    for (int w = 0; w < 8; w++) var += red[w];
    var *= (1.0f / 512.0f);

    const float inv = rsqrtf(var + LN_EPS);
    float y0 = d0 * inv * g[t]       + b[t];
    float y1 = d1 * inv * g[t + 256] + b[t + 256];
    if (ACT) {
        y0 = y0 > 0.f ? y0 : (__expf(y0) - 1.0f);
        y1 = y1 > 0.f ? y1 : (__expf(y1) - 1.0f);
    }
    if (H16) {
        oh[(size_t)row * 512 + t]       = __float2half_rn(y0);
        oh[(size_t)row * 512 + t + 256] = __float2half_rn(y1);
    } else {
        of[(size_t)row * 512 + t]       = y0;
        of[(size_t)row * 512 + t + 256] = y1;
    }
}

// ---------------------------------------------------------------------------
// Neighbor attention (one warp per node). fp16 q/k/v in, fp16 out.
// ---------------------------------------------------------------------------
__global__ void __launch_bounds__(256)
nbr_attn(const __half* __restrict__ q, const __half* __restrict__ kc,
         const __half* __restrict__ vc, const int* __restrict__ nbrs,
         __half* __restrict__ oh) {
    const int warp = threadIdx.x >> 5;
    const int lane = threadIdx.x & 31;
    const int node = blockIdx.x * 8 + warp;

    const size_t base = (size_t)node * 512 + lane * 16;
    float qr[16];
    {
        uint4 u0 = *(const uint4*)(q + base);
        uint4 u1 = *(const uint4*)(q + base + 8);
        h8_to_f(u0, qr); h8_to_f(u1, qr + 8);
    }

    float m = -1e30f, s = 0.f;
    float acc[16];
#pragma unroll
    for (int i = 0; i < 16; i++) acc[i] = 0.f;

#pragma unroll
    for (int j = 0; j < KNBR; j++) {
        const int nb = __ldg(&nbrs[node * KNBR + j]);
        const __half* kp = kc + (size_t)nb * 512 + lane * 16;
        const __half* vp = vc + (size_t)nb * 512 + lane * 16;

        float kr[16], vr[16];
        uint4 k0 = *(const uint4*)kp;
        uint4 k1 = *(const uint4*)(kp + 8);
        uint4 v0 = *(const uint4*)vp;
        uint4 v1 = *(const uint4*)(vp + 8);
        h8_to_f(k0, kr); h8_to_f(k1, kr + 8);
        h8_to_f(v0, vr); h8_to_f(v1, vr + 8);

        float dot = 0.f;
#pragma unroll
        for (int i = 0; i < 16; i++) dot = fmaf(kr[i], qr[i], dot);
        dot += __shfl_xor_sync(0xffffffffu, dot, 1);
        dot += __shfl_xor_sync(0xffffffffu, dot, 2);
        const float score = dot * 0.125f;

        const float mn   = fmaxf(m, score);
        const float corr = __expf(m - mn);
        const float p    = __expf(score - mn);
        s = s * corr + p;
#pragma unroll
        for (int i = 0; i < 16; i++) acc[i] = acc[i] * corr + p * vr[i];
        m = mn;
    }

    const float inv = 1.f / s;
    uint32_t ph[8];
#pragma unroll
    for (int j = 0; j < 8; j++)
        ph[j] = pack_h2(acc[2 * j] * inv, acc[2 * j + 1] * inv);
    *(uint4*)(oh + base)     = make_uint4(ph[0], ph[1], ph[2], ph[3]);
    *(uint4*)(oh + base + 8) = make_uint4(ph[4], ph[5], ph[6], ph[7]);
}

// ---------------------------------------------------------------------------
// Launch
// ---------------------------------------------------------------------------
extern "C" void kernel_launch(void* const* d_in, const int* in_sizes, int n_in,
                              void* d_out, int out_size) {
    (void)in_sizes; (void)n_in; (void)out_size;
    const float* data   = (const float*)d_in[0];
    const int*   nbrs   = (const int*)  d_in[1];
    const float* mlp_w0 = (const float*)d_in[2];
    const float* mlp_b0 = (const float*)d_in[3];
    const float* mlp_w1 = (const float*)d_in[4];
    const float* mlp_b1 = (const float*)d_in[5];
    const float* mlp_w2 = (const float*)d_in[6];
    const float* mlp_b2 = (const float*)d_in[7];
    const float* pd_w   = (const float*)d_in[8];
    const float* pd_b   = (const float*)d_in[9];
    const float* pi_w   = (const float*)d_in[10];
    const float* pi_b   = (const float*)d_in[11];
    const float* q_w    = (const float*)d_in[12];
    const float* q_b    = (const float*)d_in[13];
    const float* k_w    = (const float*)d_in[14];
    const float* k_b    = (const float*)d_in[15];
    const float* v_w    = (const float*)d_in[16];
    const float* v_b    = (const float*)d_in[17];
    const float* o_w    = (const float*)d_in[18];
    const float* o_b    = (const float*)d_in[19];
    const float* ln1_g  = (const float*)d_in[20];
    const float* ln1_b  = (const float*)d_in[21];
    const float* ln2_g  = (const float*)d_in[22];
    const float* ln2_b  = (const float*)d_in[23];
    float* out = (float*)d_out;

    __half *data_h, *h1_h, *h2_h, *loc_h, *at_h, *qh, *kh, *vh;
    float *h3, *pd, *inter, *pi;
    __half *w0t, *w1t, *w2t, *pdt, *pit, *qt, *kt, *vt, *ot;
    cudaGetSymbolAddress((void**)&data_h, g_data_h);
    cudaGetSymbolAddress((void**)&h1_h, g_h1_h);
    cudaGetSymbolAddress((void**)&h2_h, g_h2_h);
    cudaGetSymbolAddress((void**)&loc_h, g_loc_h);
    cudaGetSymbolAddress((void**)&at_h, g_at_h);
    cudaGetSymbolAddress((void**)&qh, g_qh);   cudaGetSymbolAddress((void**)&kh, g_kh);
    cudaGetSymbolAddress((void**)&vh, g_vh);
    cudaGetSymbolAddress((void**)&h3, g_h3);   cudaGetSymbolAddress((void**)&pd, g_pd);
    cudaGetSymbolAddress((void**)&inter, g_inter);
    cudaGetSymbolAddress((void**)&pi, g_pi);
    cudaGetSymbolAddress((void**)&w0t, g_w0t); cudaGetSymbolAddress((void**)&w1t, g_w1t);
    cudaGetSymbolAddress((void**)&w2t, g_w2t); cudaGetSymbolAddress((void**)&pdt, g_pdt);
    cudaGetSymbolAddress((void**)&pit, g_pit); cudaGetSymbolAddress((void**)&qt,  g_qt);
    cudaGetSymbolAddress((void**)&kt,  g_kt);  cudaGetSymbolAddress((void**)&vt,  g_vt);
    cudaGetSymbolAddress((void**)&ot,  g_ot);

    cudaFuncSetAttribute(gemm_hmma, cudaFuncAttributeMaxDynamicSharedMemorySize, GEMM_SMEM);

    WJobs wjobs;
    wjobs.j[0] = {mlp_w0, w0t, 256};
    wjobs.j[1] = {mlp_w1, w1t, 512};
    wjobs.j[2] = {mlp_w2, w2t, 512};
    wjobs.j[3] = {pd_w,   pdt, 256};
    wjobs.j[4] = {pi_w,   pit, 256};
    wjobs.j[5] = {q_w,    qt,  512};
    wjobs.j[6] = {k_w,    kt,  512};
    wjobs.j[7] = {v_w,    vt,  512};
    wjobs.j[8] = {o_w,    ot,  512};

    const dim3 gg1(8, 128, 1);   // BN=64 -> 8 column tiles
    const dim3 gg3(8, 128, 3);

    GJob z{nullptr, nullptr, nullptr, nullptr, nullptr, 0};

    // group 1: data @ {mlp0 | pd | pi}, K=256
    GJobs jA;
    jA.j[0] = {data_h, w0t, mlp_b0, nullptr, h1_h, 1};
    jA.j[1] = {data_h, pdt, pd_b,   pd,      nullptr, 0};
    jA.j[2] = {data_h, pit, pi_b,   pi,      nullptr, 0};
    // group 2: loc @ {q | k | v}, K=512
    GJobs jQ;
    jQ.j[0] = {loc_h, qt, q_b, nullptr, qh, 0};
    jQ.j[1] = {loc_h, kt, k_b, nullptr, kh, 0};
    jQ.j[2] = {loc_h, vt, v_b, nullptr, vh, 0};
    // singles
    GJobs j1; j1.j[0] = {h1_h, w1t, mlp_b1, nullptr, h2_h, 1};  j1.j[1] = z; j1.j[2] = z;
    GJobs j2; j2.j[0] = {h2_h, w2t, mlp_b2, h3, nullptr, 0};    j2.j[1] = z; j2.j[2] = z;
    GJobs jO; jO.j[0] = {at_h, ot,  o_b,    inter, nullptr, 0}; jO.j[1] = z; jO.j[2] = z;

    // 0: all weight transposes (fp16 round)
    wsplit_all<<<dim3(16, 16, 9), dim3(32, 8)>>>(wjobs);
    // 1: data -> fp16
    split_f32<<<(NROW * IN_DIM) / (256 * 8), 256>>>(data, data_h, NROW * IN_DIM);
    // 2: z-batched data GEMMs (mlp0 | pd | pi)
    gemm_hmma<<<gg3, 256, GEMM_SMEM>>>(jA, 256);
    // 3: h1 @ w1 -> h2
    gemm_hmma<<<gg1, 256, GEMM_SMEM>>>(j1, 512);
    // 4: h2 @ w2 -> h3
    gemm_hmma<<<gg1, 256, GEMM_SMEM>>>(j2, 512);
    // 5: local = elu(LN(h3 + 2*pd)) -> fp16
    ln_res<1, 1><<<NROW, 256>>>(h3, pd, 2.0f, ln1_g, ln1_b, nullptr, loc_h);
    // 6: z-batched QKV GEMMs
    gemm_hmma<<<gg3, 256, GEMM_SMEM>>>(jQ, 512);
    // 7: neighbor attention (fp16 gather) -> fp16
    nbr_attn<<<NROW / 8, 256>>>(qh, kh, vh, nbrs, at_h);
    // 8: attn @ o_w -> inter
    gemm_hmma<<<gg1, 256, GEMM_SMEM>>>(jO, 512);
    // 9: out = LN(inter + pi)
    ln_res<0, 0><<<NROW, 256>>>(inter, pi, 1.0f, ln2_g, ln2_b, out, nullptr);
}